// round 13
// baseline (speedup 1.0000x reference)
#include <cuda_runtime.h>
#include <cuda_bf16.h>
#include <cstdint>

#define Bb   32
#define Ll   128
#define Hh   512
#define ENn  256
#define ETt  512
#define XD   768      // EN+ET
#define KIN  1536     // 3*H
#define Vv   10053
#define EOFN 299
#define EOFT 9999

#define VCH  2514     // out chunk (4 chunks: 2514*3 + 2511)
#define NCH  4

#define WG_VPT 10     // v-rows per thread
#define WG_YW  8      // y warps
#define WG_VB  (WG_VPT * WG_YW)   // 80 v per block
#define WG_KC  64     // k-chunk staged in smem
#define WG_BLOCKS ((Vv + WG_VB - 1) / WG_VB)   // 126

// ---------------- device state (no allocs allowed) ----------------
__device__ float g_hT[2][Hh * Bb];              // ping-pong hidden, [k][b]
__device__ float g_c[Bb * Hh];                  // cell, [b][h]
__device__ float g_hs[Bb * Ll * Hh];            // stored hiddens [b][l][h]
__device__ float g_x_all[(size_t)Ll * XD * Bb]; // all embedded inputs [t][k][b]
__device__ float g_inT[KIN * Bb];               // Wg input, transposed [k][b]
__device__ float g_logits[Bb * Vv];             // [b][v]
__device__ float g_s[Bb];
__device__ float g_pm[Bb * NCH];
__device__ float g_pse[Bb * NCH];
__device__ float g_psl[Bb * NCH];
__device__ int   g_pa[Bb * NCH];

// packed fp32x2 helpers (sm_100+)
__device__ __forceinline__ void ffma2(unsigned long long &a, unsigned long long x, unsigned long long y) {
    asm("fma.rn.f32x2 %0, %1, %2, %0;" : "+l"(a) : "l"(x), "l"(y));
}
__device__ __forceinline__ unsigned long long pack2(float lo, float hi) {
    unsigned long long r; asm("mov.b64 %0, {%1,%2};" : "=l"(r) : "f"(lo), "f"(hi)); return r;
}
__device__ __forceinline__ float2 up2(unsigned long long a) {
    float2 r; asm("mov.b64 {%0,%1}, %2;" : "=f"(r.x), "=f"(r.y) : "l"(a)); return r;
}
__device__ __forceinline__ float sigm(float x) { return 1.0f / (1.0f + expf(-x)); }

// ---------------- init ----------------
__global__ void init_kernel(float* out) {
    size_t i = (size_t)blockIdx.x * blockDim.x + threadIdx.x;
    size_t n = (size_t)Bb * Ll * Hh;
    for (size_t j = i; j < n; j += (size_t)gridDim.x * blockDim.x) g_hs[j] = 0.0f;
    if (i < (size_t)Hh * Bb) g_hT[0][i] = 0.0f;
    if (i < (size_t)Bb * Hh) g_c[i] = 0.0f;
    if (i == 0) out[0] = 0.0f;
}

// ---------------- embed ALL timesteps upfront: x[t][k][b] ----------------
__global__ void embed_all_kernel(const int* __restrict__ n_ten, const int* __restrict__ t_ten,
                                 const float* __restrict__ embN, const float* __restrict__ embT) {
    int t = blockIdx.y;
    int idx = blockIdx.x * 256 + threadIdx.x;     // 96*256 = 24576 = XD*Bb exactly
    int b = idx / XD, k = idx % XD;
    int in_n = (t == 0) ? 0 : n_ten[b * Ll + t - 1];
    int in_t = (t == 0) ? 0 : t_ten[b * Ll + t - 1];
    float v = (k < ENn) ? embN[in_n * ENn + k] : embT[(size_t)in_t * ETt + (k - ENn)];
    g_x_all[(size_t)t * XD * Bb + k * Bb + b] = v;
}

// ---------------- LSTM (f32x2 packed), also writes h/c into g_inT ----------------
__global__ __launch_bounds__(256) void lstm_kernel(int t, int pp,
        const float* __restrict__ w_ih, const float* __restrict__ w_hh,
        const float* __restrict__ b_ih, const float* __restrict__ b_hh) {
    int b = threadIdx.x;                      // lane = batch
    int h = blockIdx.x * blockDim.y + threadIdx.y;
    const float* hin = g_hT[pp];
    float* hout = g_hT[pp ^ 1];
    const float* xin = g_x_all + (size_t)t * XD * Bb;

    unsigned long long Ai0 = 0, Ai1 = 0, Af0 = 0, Af1 = 0, Ag0 = 0, Ag1 = 0, Ao0 = 0, Ao1 = 0;

    const ulonglong2* wi0 = (const ulonglong2*)(w_ih + (size_t)h * XD);
    const ulonglong2* wi1 = (const ulonglong2*)(w_ih + (size_t)(Hh + h) * XD);
    const ulonglong2* wi2 = (const ulonglong2*)(w_ih + (size_t)(2 * Hh + h) * XD);
    const ulonglong2* wi3 = (const ulonglong2*)(w_ih + (size_t)(3 * Hh + h) * XD);
    #pragma unroll 4
    for (int kk = 0; kk < XD / 4; kk++) {
        float x0 = xin[(4 * kk + 0) * Bb + b];
        float x1 = xin[(4 * kk + 1) * Bb + b];
        float x2 = xin[(4 * kk + 2) * Bb + b];
        float x3 = xin[(4 * kk + 3) * Bb + b];
        unsigned long long p01 = pack2(x0, x1), p23 = pack2(x2, x3);
        ulonglong2 w;
        w = wi0[kk]; ffma2(Ai0, w.x, p01); ffma2(Ai1, w.y, p23);
        w = wi1[kk]; ffma2(Af0, w.x, p01); ffma2(Af1, w.y, p23);
        w = wi2[kk]; ffma2(Ag0, w.x, p01); ffma2(Ag1, w.y, p23);
        w = wi3[kk]; ffma2(Ao0, w.x, p01); ffma2(Ao1, w.y, p23);
    }
    const ulonglong2* wh0 = (const ulonglong2*)(w_hh + (size_t)h * Hh);
    const ulonglong2* wh1 = (const ulonglong2*)(w_hh + (size_t)(Hh + h) * Hh);
    const ulonglong2* wh2 = (const ulonglong2*)(w_hh + (size_t)(2 * Hh + h) * Hh);
    const ulonglong2* wh3 = (const ulonglong2*)(w_hh + (size_t)(3 * Hh + h) * Hh);
    #pragma unroll 4
    for (int kk = 0; kk < Hh / 4; kk++) {
        float x0 = hin[(4 * kk + 0) * Bb + b];
        float x1 = hin[(4 * kk + 1) * Bb + b];
        float x2 = hin[(4 * kk + 2) * Bb + b];
        float x3 = hin[(4 * kk + 3) * Bb + b];
        unsigned long long p01 = pack2(x0, x1), p23 = pack2(x2, x3);
        ulonglong2 w;
        w = wh0[kk]; ffma2(Ai0, w.x, p01); ffma2(Ai1, w.y, p23);
        w = wh1[kk]; ffma2(Af0, w.x, p01); ffma2(Af1, w.y, p23);
        w = wh2[kk]; ffma2(Ag0, w.x, p01); ffma2(Ag1, w.y, p23);
        w = wh3[kk]; ffma2(Ao0, w.x, p01); ffma2(Ao1, w.y, p23);
    }
    float2 u, v2;
    u = up2(Ai0); v2 = up2(Ai1); float ai = b_ih[h]          + b_hh[h]          + u.x + u.y + v2.x + v2.y;
    u = up2(Af0); v2 = up2(Af1); float af = b_ih[Hh + h]     + b_hh[Hh + h]     + u.x + u.y + v2.x + v2.y;
    u = up2(Ag0); v2 = up2(Ag1); float ag = b_ih[2 * Hh + h] + b_hh[2 * Hh + h] + u.x + u.y + v2.x + v2.y;
    u = up2(Ao0); v2 = up2(Ao1); float ao = b_ih[3 * Hh + h] + b_hh[3 * Hh + h] + u.x + u.y + v2.x + v2.y;

    float ig = sigm(ai), fg = sigm(af), gg = tanhf(ag), og = sigm(ao);
    float c  = g_c[b * Hh + h];
    float cn = fg * c + ig * gg;
    float hn = og * tanhf(cn);
    g_c[b * Hh + h] = cn;
    hout[h * Bb + b] = hn;
    g_hs[((size_t)b * Ll + t) * Hh + h] = hn;
    g_inT[h * Bb + b] = hn;              // coalesced [k][b] writes
    g_inT[(Hh + h) * Bb + b] = cn;
}

// ---------------- prep: s = sigmoid([h,c]@Ws) + parent gather ----------------
__global__ __launch_bounds__(256) void prep_kernel(int t, const int* __restrict__ p_ten,
        const float* __restrict__ Ws_w, const float* __restrict__ Ws_b) {
    __shared__ float red[256];
    int b = blockIdx.x, tid = threadIdx.x;
    const float* hrow = g_hs + ((size_t)b * Ll + t) * Hh;
    const float* crow = g_c + (size_t)b * Hh;
    float sp = 0.0f;
    for (int k = tid; k < Hh; k += 256) sp += hrow[k] * Ws_w[k] + crow[k] * Ws_w[Hh + k];
    red[tid] = sp;
    // parent: reference reads hs BEFORE writing index t -> par==t must see zero,
    // par>t sees zero (never written), par<t sees stored value
    int par = (t == 0) ? 0 : p_ten[b * Ll + t - 1];
    bool pz = (par == t);
    const float* prow = g_hs + ((size_t)b * Ll + par) * Hh;
    for (int k = tid; k < Hh; k += 256)
        g_inT[(2 * Hh + k) * Bb + b] = pz ? 0.0f : prow[k];
    __syncthreads();
    for (int off = 128; off >= 1; off >>= 1) {
        if (tid < off) red[tid] += red[tid + off];
        __syncthreads();
    }
    if (tid == 0) g_s[b] = sigm(red[0] + Ws_b[0]);
}

// ---------------- Wg GEMM: smem-tiled, f32x2 accumulate ----------------
__global__ __launch_bounds__(256) void wg_kernel(const float* __restrict__ Wg_w,
                                                 const float* __restrict__ Wg_b) {
    __shared__ __align__(16) float wsh[WG_VB * WG_KC];   // 80*64*4 = 20 KB
    __shared__ __align__(16) float xsh[WG_KC * Bb];      //  64*32*4 =  8 KB
    int b = threadIdx.x, y = threadIdx.y;
    int tid = y * 32 + b;
    int v0 = blockIdx.x * WG_VB;

    unsigned long long a0[WG_VPT], a1[WG_VPT];
    #pragma unroll
    for (int i = 0; i < WG_VPT; i++) { a0[i] = 0ull; a1[i] = 0ull; }

    for (int kc = 0; kc < KIN; kc += WG_KC) {
        // stage W[80][64] coalesced
        #pragma unroll
        for (int i = tid; i < WG_VB * (WG_KC / 4); i += 256) {
            int r  = i / (WG_KC / 4);
            int cc = i % (WG_KC / 4);
            int vv = v0 + r; if (vv >= Vv) vv = Vv - 1;
            ((float4*)(wsh + r * WG_KC))[cc] =
                ((const float4*)(Wg_w + (size_t)vv * KIN + kc))[cc];
        }
        // stage X[64][32] — flat copy, same layout as g_inT
        #pragma unroll
        for (int i = tid; i < WG_KC * Bb; i += 256)
            xsh[i] = g_inT[kc * Bb + i];
        __syncthreads();

        #pragma unroll 2
        for (int kk = 0; kk < WG_KC / 4; kk++) {
            float x0 = xsh[(4 * kk + 0) * Bb + b];
            float x1 = xsh[(4 * kk + 1) * Bb + b];
            float x2 = xsh[(4 * kk + 2) * Bb + b];
            float x3 = xsh[(4 * kk + 3) * Bb + b];
            unsigned long long p01 = pack2(x0, x1), p23 = pack2(x2, x3);
            #pragma unroll
            for (int i = 0; i < WG_VPT; i++) {
                int r = y * WG_VPT + i;
                ulonglong2 wv = ((const ulonglong2*)(wsh + r * WG_KC))[kk];  // uniform -> broadcast
                ffma2(a0[i], wv.x, p01);
                ffma2(a1[i], wv.y, p23);
            }
        }
        __syncthreads();
    }
    #pragma unroll
    for (int i = 0; i < WG_VPT; i++) {
        int v = v0 + y * WG_VPT + i;
        if (v < Vv) {
            float2 p0 = up2(a0[i]), p1 = up2(a1[i]);
            g_logits[(size_t)b * Vv + v] = (p0.x + p1.x) + (p0.y + p1.y) + Wg_b[v];
        }
    }
}

// ---------------- out pass 1: per-chunk max/argmax/sumexp/sumlogit ----------------
__global__ __launch_bounds__(256) void out_partial_kernel() {
    __shared__ float st[VCH];
    __shared__ float rm[8], rse[8], rsl[8];
    __shared__ int   ra[8];
    __shared__ float Msh;
    int b = blockIdx.x, ch = blockIdx.y, tid = threadIdx.x, warp = tid >> 5, lane = tid & 31;
    int v0 = ch * VCH;
    int n  = Vv - v0; if (n > VCH) n = VCH;
    const float* lrow = g_logits + (size_t)b * Vv + v0;

    float m = -3.4e38f; int mi = 1 << 30; float sl = 0.0f;
    for (int i = tid; i < n; i += 256) {
        float x = lrow[i]; st[i] = x; sl += x;
        if (x > m) { m = x; mi = i; }
    }
    for (int o = 16; o; o >>= 1) {
        float om = __shfl_xor_sync(0xffffffffu, m, o);
        int   oi = __shfl_xor_sync(0xffffffffu, mi, o);
        if (om > m || (om == m && oi < mi)) { m = om; mi = oi; }
        sl += __shfl_xor_sync(0xffffffffu, sl, o);
    }
    if (lane == 0) { rm[warp] = m; ra[warp] = mi; rsl[warp] = sl; }
    __syncthreads();
    if (tid == 0) {
        for (int w = 1; w < 8; w++)
            if (rm[w] > rm[0] || (rm[w] == rm[0] && ra[w] < ra[0])) { rm[0] = rm[w]; ra[0] = ra[w]; }
        Msh = rm[0];
    }
    __syncthreads();
    float M = Msh, se = 0.0f;
    for (int i = tid; i < n; i += 256) se += expf(st[i] - M);
    for (int o = 16; o; o >>= 1) se += __shfl_xor_sync(0xffffffffu, se, o);
    if (lane == 0) rse[warp] = se;
    __syncthreads();
    if (tid == 0) {
        float SE = 0.0f, SL = 0.0f;
        for (int w = 0; w < 8; w++) { SE += rse[w]; SL += rsl[w]; }
        g_pm[b * NCH + ch]  = rm[0];
        g_pa[b * NCH + ch]  = ra[0] + v0;
        g_pse[b * NCH + ch] = SE;
        g_psl[b * NCH + ch] = SL;
    }
}

// ---------------- out pass 2: merge chunks, KL term, topi ----------------
// NOTE: pointer branch provably never taken (s*log_softmax <= 0 < (1-s)*attn_w),
// so the attention path is dead code and topi = argmax(logits).
__global__ void out_final_kernel(int t, const int* __restrict__ t_ten, float* __restrict__ out) {
    int b = blockIdx.x;
    if (threadIdx.x != 0) return;
    float M = g_pm[b * NCH]; int ai = g_pa[b * NCH];
    for (int ch = 1; ch < NCH; ch++) {
        float m = g_pm[b * NCH + ch];
        if (m > M) { M = m; ai = g_pa[b * NCH + ch]; }
    }
    float SE = 0.0f, SL = 0.0f;
    for (int ch = 0; ch < NCH; ch++) {
        SE += g_pse[b * NCH + ch] * expf(g_pm[b * NCH + ch] - M);
        SL += g_psl[b * NCH + ch];
    }
    float lse = M + logf(SE);
    float s = g_s[b];
    int tcol = t_ten[b * Ll + t];
    const float* lrow = g_logits + (size_t)b * Vv;
    float sout = s * (SL - (float)Vv * lse);
    float oeof = s * (lrow[EOFT] - lse);
    float otc  = s * (lrow[tcol] - lse);
    const float SMV = 0.1f / 10051.0f;
    float MPLOG = 0.1f * logf(SMV) + 0.9f * logf(0.9f);
    float tl = MPLOG - (SMV * (sout - oeof - otc) + 0.9f * otc);
    if (tcol == EOFT) tl = 0.0f;
    atomicAdd(out, tl);
    out[1 + b * Ll + t] = (float)ai;
}

// ---------------- host ----------------
extern "C" void kernel_launch(void* const* d_in, const int* in_sizes, int n_in,
                              void* d_out, int out_size) {
    const int*   n_ten = (const int*)d_in[0];
    const int*   t_ten = (const int*)d_in[1];
    const int*   p_ten = (const int*)d_in[2];
    const float* embN  = (const float*)d_in[3];
    const float* embT  = (const float*)d_in[4];
    const float* w_ih  = (const float*)d_in[5];
    const float* w_hh  = (const float*)d_in[6];
    const float* b_ih  = (const float*)d_in[7];
    const float* b_hh  = (const float*)d_in[8];
    // d_in[9..12]: Wh_w, Wh_b, v_w, v_b — attention is dead code, unused
    const float* Wg_w  = (const float*)d_in[13];
    const float* Wg_b  = (const float*)d_in[14];
    const float* Ws_w  = (const float*)d_in[15];
    const float* Ws_b  = (const float*)d_in[16];
    float* out = (float*)d_out;

    init_kernel<<<2048, 256>>>(out);
    embed_all_kernel<<<dim3(96, Ll), 256>>>(n_ten, t_ten, embN, embT);
    for (int t = 0; t < Ll; t++) {
        lstm_kernel<<<Hh / 8, dim3(Bb, 8)>>>(t, t & 1, w_ih, w_hh, b_ih, b_hh);
        prep_kernel<<<Bb, 256>>>(t, p_ten, Ws_w, Ws_b);
        wg_kernel<<<WG_BLOCKS, dim3(Bb, WG_YW)>>>(Wg_w, Wg_b);
        out_partial_kernel<<<dim3(Bb, NCH), 256>>>();
        out_final_kernel<<<Bb, 32>>>(t, t_ten, out);
    }
}

// round 14
// speedup vs baseline: 1.0089x; 1.0089x over previous
#include <cuda_runtime.h>
#include <cuda_bf16.h>
#include <cstdint>

#define Bb   32
#define Ll   128
#define Hh   512
#define ENn  256
#define ETt  512
#define XD   768      // EN+ET
#define KIN  1536     // 3*H
#define Vv   10053
#define EOFN 299
#define EOFT 9999

#define VCH  2514     // out chunk (4 chunks: 2514*3 + 2511)
#define NCH  4

#define WG_VPT 10     // v-rows per thread
#define WG_YW  8      // y warps
#define WG_VB  (WG_VPT * WG_YW)   // 80 v per block
#define WG_KC  64     // k-chunk staged in smem
#define WG_BLOCKS ((Vv + WG_VB - 1) / WG_VB)   // 126

// ---------------- device state (no allocs allowed) ----------------
__device__ float g_hT[2][Hh * Bb];              // ping-pong hidden, [k][b]
__device__ float g_c[Bb * Hh];                  // cell, [b][h]
__device__ float g_hs[Bb * Ll * Hh];            // stored hiddens [b][l][h]
__device__ float g_x_all[(size_t)Ll * XD * Bb]; // all embedded inputs [t][k][b]
__device__ float g_inT[KIN * Bb];               // Wg input, transposed [k][b]
__device__ float g_logits[Bb * Vv];             // [b][v]
__device__ float g_s[Bb];
__device__ float g_pm[Bb * NCH];
__device__ float g_pse[Bb * NCH];
__device__ float g_psl[Bb * NCH];
__device__ int   g_pa[Bb * NCH];

// packed fp32x2 helpers (sm_100+)
__device__ __forceinline__ void ffma2(unsigned long long &a, unsigned long long x, unsigned long long y) {
    asm("fma.rn.f32x2 %0, %1, %2, %0;" : "+l"(a) : "l"(x), "l"(y));
}
__device__ __forceinline__ unsigned long long pack2(float lo, float hi) {
    unsigned long long r; asm("mov.b64 %0, {%1,%2};" : "=l"(r) : "f"(lo), "f"(hi)); return r;
}
__device__ __forceinline__ float2 up2(unsigned long long a) {
    float2 r; asm("mov.b64 {%0,%1}, %2;" : "=f"(r.x), "=f"(r.y) : "l"(a)); return r;
}
__device__ __forceinline__ float sigm(float x) { return 1.0f / (1.0f + expf(-x)); }

// ---------------- init ----------------
__global__ void init_kernel(float* out) {
    size_t i = (size_t)blockIdx.x * blockDim.x + threadIdx.x;
    size_t n = (size_t)Bb * Ll * Hh;
    for (size_t j = i; j < n; j += (size_t)gridDim.x * blockDim.x) g_hs[j] = 0.0f;
    if (i < (size_t)Hh * Bb) g_hT[0][i] = 0.0f;
    if (i < (size_t)Bb * Hh) g_c[i] = 0.0f;
    if (i == 0) out[0] = 0.0f;
}

// ---------------- embed ALL timesteps upfront: x[t][k][b] ----------------
__global__ void embed_all_kernel(const int* __restrict__ n_ten, const int* __restrict__ t_ten,
                                 const float* __restrict__ embN, const float* __restrict__ embT) {
    int t = blockIdx.y;
    int idx = blockIdx.x * 256 + threadIdx.x;     // 96*256 = 24576 = XD*Bb exactly
    int b = idx / XD, k = idx % XD;
    int in_n = (t == 0) ? 0 : n_ten[b * Ll + t - 1];
    int in_t = (t == 0) ? 0 : t_ten[b * Ll + t - 1];
    float v = (k < ENn) ? embN[in_n * ENn + k] : embT[(size_t)in_t * ETt + (k - ENn)];
    g_x_all[(size_t)t * XD * Bb + k * Bb + b] = v;
}

// ---------------- LSTM (f32x2 packed), also writes h/c into g_inT ----------------
__global__ __launch_bounds__(256) void lstm_kernel(int t, int pp,
        const float* __restrict__ w_ih, const float* __restrict__ w_hh,
        const float* __restrict__ b_ih, const float* __restrict__ b_hh) {
    int b = threadIdx.x;                      // lane = batch
    int h = blockIdx.x * blockDim.y + threadIdx.y;
    const float* hin = g_hT[pp];
    float* hout = g_hT[pp ^ 1];
    const float* xin = g_x_all + (size_t)t * XD * Bb;

    unsigned long long Ai0 = 0, Ai1 = 0, Af0 = 0, Af1 = 0, Ag0 = 0, Ag1 = 0, Ao0 = 0, Ao1 = 0;

    const ulonglong2* wi0 = (const ulonglong2*)(w_ih + (size_t)h * XD);
    const ulonglong2* wi1 = (const ulonglong2*)(w_ih + (size_t)(Hh + h) * XD);
    const ulonglong2* wi2 = (const ulonglong2*)(w_ih + (size_t)(2 * Hh + h) * XD);
    const ulonglong2* wi3 = (const ulonglong2*)(w_ih + (size_t)(3 * Hh + h) * XD);
    #pragma unroll 4
    for (int kk = 0; kk < XD / 4; kk++) {
        float x0 = xin[(4 * kk + 0) * Bb + b];
        float x1 = xin[(4 * kk + 1) * Bb + b];
        float x2 = xin[(4 * kk + 2) * Bb + b];
        float x3 = xin[(4 * kk + 3) * Bb + b];
        unsigned long long p01 = pack2(x0, x1), p23 = pack2(x2, x3);
        ulonglong2 w;
        w = wi0[kk]; ffma2(Ai0, w.x, p01); ffma2(Ai1, w.y, p23);
        w = wi1[kk]; ffma2(Af0, w.x, p01); ffma2(Af1, w.y, p23);
        w = wi2[kk]; ffma2(Ag0, w.x, p01); ffma2(Ag1, w.y, p23);
        w = wi3[kk]; ffma2(Ao0, w.x, p01); ffma2(Ao1, w.y, p23);
    }
    const ulonglong2* wh0 = (const ulonglong2*)(w_hh + (size_t)h * Hh);
    const ulonglong2* wh1 = (const ulonglong2*)(w_hh + (size_t)(Hh + h) * Hh);
    const ulonglong2* wh2 = (const ulonglong2*)(w_hh + (size_t)(2 * Hh + h) * Hh);
    const ulonglong2* wh3 = (const ulonglong2*)(w_hh + (size_t)(3 * Hh + h) * Hh);
    #pragma unroll 4
    for (int kk = 0; kk < Hh / 4; kk++) {
        float x0 = hin[(4 * kk + 0) * Bb + b];
        float x1 = hin[(4 * kk + 1) * Bb + b];
        float x2 = hin[(4 * kk + 2) * Bb + b];
        float x3 = hin[(4 * kk + 3) * Bb + b];
        unsigned long long p01 = pack2(x0, x1), p23 = pack2(x2, x3);
        ulonglong2 w;
        w = wh0[kk]; ffma2(Ai0, w.x, p01); ffma2(Ai1, w.y, p23);
        w = wh1[kk]; ffma2(Af0, w.x, p01); ffma2(Af1, w.y, p23);
        w = wh2[kk]; ffma2(Ag0, w.x, p01); ffma2(Ag1, w.y, p23);
        w = wh3[kk]; ffma2(Ao0, w.x, p01); ffma2(Ao1, w.y, p23);
    }
    float2 u, v2;
    u = up2(Ai0); v2 = up2(Ai1); float ai = b_ih[h]          + b_hh[h]          + u.x + u.y + v2.x + v2.y;
    u = up2(Af0); v2 = up2(Af1); float af = b_ih[Hh + h]     + b_hh[Hh + h]     + u.x + u.y + v2.x + v2.y;
    u = up2(Ag0); v2 = up2(Ag1); float ag = b_ih[2 * Hh + h] + b_hh[2 * Hh + h] + u.x + u.y + v2.x + v2.y;
    u = up2(Ao0); v2 = up2(Ao1); float ao = b_ih[3 * Hh + h] + b_hh[3 * Hh + h] + u.x + u.y + v2.x + v2.y;

    float ig = sigm(ai), fg = sigm(af), gg = tanhf(ag), og = sigm(ao);
    float c  = g_c[b * Hh + h];
    float cn = fg * c + ig * gg;
    float hn = og * tanhf(cn);
    g_c[b * Hh + h] = cn;
    hout[h * Bb + b] = hn;
    g_hs[((size_t)b * Ll + t) * Hh + h] = hn;
    g_inT[h * Bb + b] = hn;              // coalesced [k][b] writes
    g_inT[(Hh + h) * Bb + b] = cn;
}

// ---------------- prep: s = sigmoid([h,c]@Ws) + parent gather ----------------
__global__ __launch_bounds__(256) void prep_kernel(int t, const int* __restrict__ p_ten,
        const float* __restrict__ Ws_w, const float* __restrict__ Ws_b) {
    __shared__ float red[256];
    int b = blockIdx.x, tid = threadIdx.x;
    const float* hrow = g_hs + ((size_t)b * Ll + t) * Hh;
    const float* crow = g_c + (size_t)b * Hh;
    float sp = 0.0f;
    for (int k = tid; k < Hh; k += 256) sp += hrow[k] * Ws_w[k] + crow[k] * Ws_w[Hh + k];
    red[tid] = sp;
    // parent: reference reads hs BEFORE writing index t -> par==t must see zero,
    // par>t sees zero (never written), par<t sees stored value
    int par = (t == 0) ? 0 : p_ten[b * Ll + t - 1];
    bool pz = (par == t);
    const float* prow = g_hs + ((size_t)b * Ll + par) * Hh;
    for (int k = tid; k < Hh; k += 256)
        g_inT[(2 * Hh + k) * Bb + b] = pz ? 0.0f : prow[k];
    __syncthreads();
    for (int off = 128; off >= 1; off >>= 1) {
        if (tid < off) red[tid] += red[tid + off];
        __syncthreads();
    }
    if (tid == 0) g_s[b] = sigm(red[0] + Ws_b[0]);
}

// ---------------- Wg GEMM: smem-tiled, f32x2 accumulate ----------------
__global__ __launch_bounds__(256) void wg_kernel(const float* __restrict__ Wg_w,
                                                 const float* __restrict__ Wg_b) {
    __shared__ __align__(16) float wsh[WG_VB * WG_KC];   // 80*64*4 = 20 KB
    __shared__ __align__(16) float xsh[WG_KC * Bb];      //  64*32*4 =  8 KB
    int b = threadIdx.x, y = threadIdx.y;
    int tid = y * 32 + b;
    int v0 = blockIdx.x * WG_VB;

    unsigned long long a0[WG_VPT], a1[WG_VPT];
    #pragma unroll
    for (int i = 0; i < WG_VPT; i++) { a0[i] = 0ull; a1[i] = 0ull; }

    for (int kc = 0; kc < KIN; kc += WG_KC) {
        // stage W[80][64] coalesced
        #pragma unroll
        for (int i = tid; i < WG_VB * (WG_KC / 4); i += 256) {
            int r  = i / (WG_KC / 4);
            int cc = i % (WG_KC / 4);
            int vv = v0 + r; if (vv >= Vv) vv = Vv - 1;
            ((float4*)(wsh + r * WG_KC))[cc] =
                ((const float4*)(Wg_w + (size_t)vv * KIN + kc))[cc];
        }
        // stage X[64][32] — flat copy, same layout as g_inT
        #pragma unroll
        for (int i = tid; i < WG_KC * Bb; i += 256)
            xsh[i] = g_inT[kc * Bb + i];
        __syncthreads();

        #pragma unroll 2
        for (int kk = 0; kk < WG_KC / 4; kk++) {
            float x0 = xsh[(4 * kk + 0) * Bb + b];
            float x1 = xsh[(4 * kk + 1) * Bb + b];
            float x2 = xsh[(4 * kk + 2) * Bb + b];
            float x3 = xsh[(4 * kk + 3) * Bb + b];
            unsigned long long p01 = pack2(x0, x1), p23 = pack2(x2, x3);
            #pragma unroll
            for (int i = 0; i < WG_VPT; i++) {
                int r = y * WG_VPT + i;
                ulonglong2 wv = ((const ulonglong2*)(wsh + r * WG_KC))[kk];  // uniform -> broadcast
                ffma2(a0[i], wv.x, p01);
                ffma2(a1[i], wv.y, p23);
            }
        }
        __syncthreads();
    }
    #pragma unroll
    for (int i = 0; i < WG_VPT; i++) {
        int v = v0 + y * WG_VPT + i;
        if (v < Vv) {
            float2 p0 = up2(a0[i]), p1 = up2(a1[i]);
            g_logits[(size_t)b * Vv + v] = (p0.x + p1.x) + (p0.y + p1.y) + Wg_b[v];
        }
    }
}

// ---------------- out pass 1: per-chunk max/argmax/sumexp/sumlogit ----------------
__global__ __launch_bounds__(256) void out_partial_kernel() {
    __shared__ float st[VCH];
    __shared__ float rm[8], rse[8], rsl[8];
    __shared__ int   ra[8];
    __shared__ float Msh;
    int b = blockIdx.x, ch = blockIdx.y, tid = threadIdx.x, warp = tid >> 5, lane = tid & 31;
    int v0 = ch * VCH;
    int n  = Vv - v0; if (n > VCH) n = VCH;
    const float* lrow = g_logits + (size_t)b * Vv + v0;

    float m = -3.4e38f; int mi = 1 << 30; float sl = 0.0f;
    for (int i = tid; i < n; i += 256) {
        float x = lrow[i]; st[i] = x; sl += x;
        if (x > m) { m = x; mi = i; }
    }
    for (int o = 16; o; o >>= 1) {
        float om = __shfl_xor_sync(0xffffffffu, m, o);
        int   oi = __shfl_xor_sync(0xffffffffu, mi, o);
        if (om > m || (om == m && oi < mi)) { m = om; mi = oi; }
        sl += __shfl_xor_sync(0xffffffffu, sl, o);
    }
    if (lane == 0) { rm[warp] = m; ra[warp] = mi; rsl[warp] = sl; }
    __syncthreads();
    if (tid == 0) {
        for (int w = 1; w < 8; w++)
            if (rm[w] > rm[0] || (rm[w] == rm[0] && ra[w] < ra[0])) { rm[0] = rm[w]; ra[0] = ra[w]; }
        Msh = rm[0];
    }
    __syncthreads();
    float M = Msh, se = 0.0f;
    for (int i = tid; i < n; i += 256) se += expf(st[i] - M);
    for (int o = 16; o; o >>= 1) se += __shfl_xor_sync(0xffffffffu, se, o);
    if (lane == 0) rse[warp] = se;
    __syncthreads();
    if (tid == 0) {
        float SE = 0.0f, SL = 0.0f;
        for (int w = 0; w < 8; w++) { SE += rse[w]; SL += rsl[w]; }
        g_pm[b * NCH + ch]  = rm[0];
        g_pa[b * NCH + ch]  = ra[0] + v0;
        g_pse[b * NCH + ch] = SE;
        g_psl[b * NCH + ch] = SL;
    }
}

// ---------------- out pass 2: merge chunks, KL term, topi ----------------
// NOTE: pointer branch provably never taken (s*log_softmax <= 0 < (1-s)*attn_w),
// so the attention path is dead code and topi = argmax(logits).
__global__ void out_final_kernel(int t, const int* __restrict__ t_ten, float* __restrict__ out) {
    int b = blockIdx.x;
    if (threadIdx.x != 0) return;
    float M = g_pm[b * NCH]; int ai = g_pa[b * NCH];
    for (int ch = 1; ch < NCH; ch++) {
        float m = g_pm[b * NCH + ch];
        if (m > M) { M = m; ai = g_pa[b * NCH + ch]; }
    }
    float SE = 0.0f, SL = 0.0f;
    for (int ch = 0; ch < NCH; ch++) {
        SE += g_pse[b * NCH + ch] * expf(g_pm[b * NCH + ch] - M);
        SL += g_psl[b * NCH + ch];
    }
    float lse = M + logf(SE);
    float s = g_s[b];
    int tcol = t_ten[b * Ll + t];
    const float* lrow = g_logits + (size_t)b * Vv;
    float sout = s * (SL - (float)Vv * lse);
    float oeof = s * (lrow[EOFT] - lse);
    float otc  = s * (lrow[tcol] - lse);
    const float SMV = 0.1f / 10051.0f;
    float MPLOG = 0.1f * logf(SMV) + 0.9f * logf(0.9f);
    float tl = MPLOG - (SMV * (sout - oeof - otc) + 0.9f * otc);
    if (tcol == EOFT) tl = 0.0f;
    atomicAdd(out, tl);
    out[1 + b * Ll + t] = (float)ai;
}

// ---------------- host ----------------
extern "C" void kernel_launch(void* const* d_in, const int* in_sizes, int n_in,
                              void* d_out, int out_size) {
    const int*   n_ten = (const int*)d_in[0];
    const int*   t_ten = (const int*)d_in[1];
    const int*   p_ten = (const int*)d_in[2];
    const float* embN  = (const float*)d_in[3];
    const float* embT  = (const float*)d_in[4];
    const float* w_ih  = (const float*)d_in[5];
    const float* w_hh  = (const float*)d_in[6];
    const float* b_ih  = (const float*)d_in[7];
    const float* b_hh  = (const float*)d_in[8];
    // d_in[9..12]: Wh_w, Wh_b, v_w, v_b — attention is dead code, unused
    const float* Wg_w  = (const float*)d_in[13];
    const float* Wg_b  = (const float*)d_in[14];
    const float* Ws_w  = (const float*)d_in[15];
    const float* Ws_b  = (const float*)d_in[16];
    float* out = (float*)d_out;

    init_kernel<<<2048, 256>>>(out);
    embed_all_kernel<<<dim3(96, Ll), 256>>>(n_ten, t_ten, embN, embT);
    for (int t = 0; t < Ll; t++) {
        lstm_kernel<<<Hh / 8, dim3(Bb, 8)>>>(t, t & 1, w_ih, w_hh, b_ih, b_hh);
        prep_kernel<<<Bb, 256>>>(t, p_ten, Ws_w, Ws_b);
        wg_kernel<<<WG_BLOCKS, dim3(Bb, WG_YW)>>>(Wg_w, Wg_b);
        out_partial_kernel<<<dim3(Bb, NCH), 256>>>();
        out_final_kernel<<<Bb, 32>>>(t, t_ten, out);
    }
}